// round 13
// baseline (speedup 1.0000x reference)
#include <cuda_runtime.h>
#include <cuda_fp16.h>
#include <cstdint>
#include <math.h>

// Problem constants
#define BB 4
#define TT 8192
#define HH 16
#define DD 64
#define CC 128                 // chunk length
#define NC (TT/CC)             // 64 chunks per sequence
#define BHN (BB*HH)            // 64 (b,h) pairs
#define NCHUNKS (BHN*NC)       // 4096 total chunks
#define EPSV 1e-6f

// Scratch (fp16): per-chunk M^T (e-major), converted in-place to exclusive prefix S_prev^T
__device__ __half g_M16[(size_t)NCHUNKS * DD * DD];   // 32 MB
__device__ float  g_z[(size_t)NCHUNKS * DD];          // 1 MB (fp32)

__device__ __forceinline__ float phi_f(float x) {
    return x > 0.f ? x + 1.f : expf(x);   // elu(x)+1
}

__device__ __forceinline__ void mma16(float* d, const uint32_t* a, const uint32_t* b) {
    asm volatile(
        "mma.sync.aligned.m16n8k16.row.col.f32.f16.f16.f32 "
        "{%0,%1,%2,%3}, {%4,%5,%6,%7}, {%8,%9}, {%0,%1,%2,%3};"
        : "+f"(d[0]), "+f"(d[1]), "+f"(d[2]), "+f"(d[3])
        : "r"(a[0]), "r"(a[1]), "r"(a[2]), "r"(a[3]), "r"(b[0]), "r"(b[1]));
}

__device__ __forceinline__ uint32_t packh2(float lo, float hi) {
    __half2 h = __floats2half2_rn(lo, hi);
    return *(uint32_t*)&h;
}
__device__ __forceinline__ uint32_t sm32(const void* p) {
    return (uint32_t)__cvta_generic_to_shared(p);
}
__device__ __forceinline__ void ldsm4(uint32_t* r, uint32_t a) {
    asm volatile("ldmatrix.sync.aligned.m8n8.x4.shared.b16 {%0,%1,%2,%3}, [%4];"
                 : "=r"(r[0]), "=r"(r[1]), "=r"(r[2]), "=r"(r[3]) : "r"(a));
}
__device__ __forceinline__ void ldsm4t(uint32_t* r, uint32_t a) {
    asm volatile("ldmatrix.sync.aligned.m8n8.x4.trans.shared.b16 {%0,%1,%2,%3}, [%4];"
                 : "=r"(r[0]), "=r"(r[1]), "=r"(r[2]), "=r"(r[3]) : "r"(a));
}

// ---------------------------------------------------------------------------
// Kernel 1: per-chunk M^T[e][d] = sum_t V[t][e] phiK[t][d], z_c = sum_t phiK.
// K,V staged NATURAL row-major [t][d] (contiguous STS); operand transposition
// via ldmatrix.trans.  grid = NCHUNKS, block = 256.
// ---------------------------------------------------------------------------
#define S1 72     // 144B row stride: /16 ok, 36 words == 4 mod 32 -> conflict-free
#define SMEM1 (2*128*S1*2 + 256*4)

__global__ void __launch_bounds__(256, 4) k1_kv(const float* __restrict__ kin,
                                                const float* __restrict__ vin) {
    extern __shared__ __align__(16) char smraw[];
    __half* sK1 = (__half*)smraw;              // [128 t][72] phiK
    __half* sV1 = sK1 + 128 * S1;              // [128 t][72] V
    float* sZ = (float*)(sV1 + 128 * S1);      // [256]

    int g = blockIdx.x;
    int bh = g >> 6, c = g & 63;
    int b = bh >> 4, h = bh & 15;
    int t0 = c * CC;
    int tid = threadIdx.x;
    int d = tid & 63, rg = tid >> 6;

    const size_t rowstride = (size_t)HH * DD;
    size_t base = ((size_t)b * TT + t0) * rowstride + (size_t)h * DD + d;

    float zacc = 0.f;
#pragma unroll 8
    for (int p = 0; p < 32; ++p) {
        int t = p * 4 + rg;
        size_t a = base + (size_t)t * rowstride;
        float pk = phi_f(kin[a]);
        zacc += pk;                               // fp32 z, unrounded
        sK1[t * S1 + d] = __float2half_rn(pk);
        sV1[t * S1 + d] = __float2half_rn(vin[a]);
    }
    sZ[tid] = zacc;
    __syncthreads();
    if (tid < 64)
        g_z[(size_t)g * 64 + tid] = sZ[tid] + sZ[tid + 64] + sZ[tid + 128] + sZ[tid + 192];

    int w = tid >> 5, lane = tid & 31;
    int gid = lane >> 2, tig = lane & 3;
    int row8 = lane & 7, seg = lane >> 3;
    int m0 = (w & 3) * 16;          // e-band (rows of M^T)
    int d0 = (w >> 2) * 32;         // d-half (cols of M^T)

    // A = V^T (m=e,k=t) from [t][e] storage: trans, m<-seg&1, k<-seg>>1
    uint32_t aVb = sm32(sV1 + (row8 + ((seg >> 1) << 3)) * S1 + m0 + ((seg & 1) << 3));
    // B = K^T (n=d,k=t) from [t][d] storage: trans, k<-seg&1, n<-seg>>1
    uint32_t bKb = sm32(sK1 + (row8 + ((seg & 1) << 3)) * S1 + d0 + ((seg >> 1) << 3));

    float acc[4][4];
#pragma unroll
    for (int i = 0; i < 4; i++)
#pragma unroll
        for (int j = 0; j < 4; j++) acc[i][j] = 0.f;

#pragma unroll
    for (int ks = 0; ks < 8; ++ks) {
        uint32_t koff = (uint32_t)(16 * ks * S1) * 2;
        uint32_t a[4];
        ldsm4t(a, aVb + koff);
#pragma unroll
        for (int np = 0; np < 2; ++np) {
            uint32_t bf4[4];
            ldsm4t(bf4, bKb + koff + np * 32);
            mma16(acc[2 * np], a, bf4 + 0);
            mma16(acc[2 * np + 1], a, bf4 + 2);
        }
    }

    __half* Mout = g_M16 + (size_t)g * DD * DD;   // [e][d]
#pragma unroll
    for (int nt = 0; nt < 4; ++nt) {
        int c0 = d0 + nt * 8 + 2 * tig;
        int r0 = m0 + gid;
        *(uint32_t*)(Mout + (size_t)r0 * DD + c0) = packh2(acc[nt][0], acc[nt][1]);
        *(uint32_t*)(Mout + (size_t)(r0 + 8) * DD + c0) = packh2(acc[nt][2], acc[nt][3]);
    }
}

// ---------------------------------------------------------------------------
// Kernel 2: exclusive prefix over chunks (fp16 data, fp32 running sums)
// ---------------------------------------------------------------------------
__global__ void __launch_bounds__(256) k2_scan() {
    int bh = blockIdx.x >> 3;
    int seg = blockIdx.x & 7;
    int u = seg * 256 + threadIdx.x;               // uint32 index, 2048 per chunk
    uint32_t* base = (uint32_t*)g_M16 + (size_t)bh * 64 * 2048 + u;

    uint32_t vals[64];
#pragma unroll
    for (int c = 0; c < 64; ++c) vals[c] = base[(size_t)c * 2048];

    float r0 = 0.f, r1 = 0.f;
#pragma unroll
    for (int c = 0; c < 64; ++c) {
        __half2 hv = *(__half2*)&vals[c];
        float a0 = __low2float(hv), a1 = __high2float(hv);
        vals[c] = packh2(r0, r1);
        r0 += a0;
        r1 += a1;
    }
#pragma unroll
    for (int c = 0; c < 64; ++c) base[(size_t)c * 2048] = vals[c];
}

__global__ void __launch_bounds__(64) k2_scanz() {
    int bh = blockIdx.x;
    size_t base = (size_t)bh * 64 * 64 + threadIdx.x;

    float vals[64];
#pragma unroll
    for (int c = 0; c < 64; ++c) vals[c] = g_z[base + (size_t)c * 64];
    float run = 0.f;
#pragma unroll
    for (int c = 0; c < 64; ++c) {
        float t = vals[c];
        vals[c] = run;
        run += t;
    }
#pragma unroll
    for (int c = 0; c < 64; ++c) g_z[base + (size_t)c * 64] = vals[c];
}

// ---------------------------------------------------------------------------
// Kernel 3: 256 threads, 8 warps, warp owns band bo = wid<4 ? wid : 11-wid.
//  - Q a-fragments loaded DIRECTLY from gmem (no sQ smem at all); qz folded in.
//  - K staged row-major [s][d]: QK B-frags non-trans ldsm.
//  - V staged row-major [t][e]: A@V B-frags via ldsm.trans (no transposed STS).
//  - S_prev^T [e][d] fp16 from g_M16: clean uint32 copy, non-trans ldsm.
// ---------------------------------------------------------------------------
#define S3 72

#define H_SK   0
#define H_SV   (H_SK + 128*S3)       // 9216
#define H_SST  (H_SV + 128*S3)       // 18432
#define H_END  (H_SST + 64*S3)       // 23040 halfs = 46 KB
#define SMEM3  (H_END*2 + 16)

__global__ void __launch_bounds__(256, 3) k3_out(const float* __restrict__ qin,
                                                 const float* __restrict__ kin,
                                                 const float* __restrict__ vin,
                                                 float* __restrict__ out) {
    extern __shared__ __align__(16) char smraw[];
    __half* sK  = (__half*)smraw + H_SK;    // [128 s][72]  phiK
    __half* sV  = (__half*)smraw + H_SV;    // [128 t][72]  V (natural)
    __half* sST = (__half*)smraw + H_SST;   // [64 e][72]   S_prev^T

    int g = blockIdx.x;
    int bh = g >> 6, c = g & 63;
    int b = bh >> 4, h = bh & 15;
    int t0 = c * CC;
    int tid = threadIdx.x;

    const size_t rowstride = (size_t)HH * DD;

    int wid = tid >> 5, lane = tid & 31;
    int gid = lane >> 2, tig = lane & 3;
    int row8 = lane & 7, seg = lane >> 3;
    int bo = (wid < 4) ? wid : (11 - wid);   // SMSP-balanced band assignment
    int r_lo = bo * 16 + gid, r_hi = r_lo + 8;

    // ---- Q a-fragments + qz, straight from gmem (warp-private operand) ----
    float qlo = 0.f, qhi = 0.f;
    uint32_t afr[4][4];
    {
        size_t qrow_lo = ((size_t)b * TT + t0 + r_lo) * rowstride + (size_t)h * DD;
        size_t qrow_hi = ((size_t)b * TT + t0 + r_hi) * rowstride + (size_t)h * DD;
        const float* zp = g_z + (size_t)g * 64;
#pragma unroll
        for (int ks = 0; ks < 4; ++ks) {
            int cc2 = 16 * ks + 2 * tig;
            float2 qa = *(const float2*)(qin + qrow_lo + cc2);
            float2 qb = *(const float2*)(qin + qrow_lo + cc2 + 8);
            float2 qc = *(const float2*)(qin + qrow_hi + cc2);
            float2 qd = *(const float2*)(qin + qrow_hi + cc2 + 8);
            float2 za = *(const float2*)(zp + cc2);
            float2 zb = *(const float2*)(zp + cc2 + 8);
            float pax = phi_f(qa.x), pay = phi_f(qa.y);
            float pbx = phi_f(qb.x), pby = phi_f(qb.y);
            float pcx = phi_f(qc.x), pcy = phi_f(qc.y);
            float pdx = phi_f(qd.x), pdy = phi_f(qd.y);
            qlo += pax * za.x + pay * za.y + pbx * zb.x + pby * zb.y;
            qhi += pcx * za.x + pcy * za.y + pdx * zb.x + pdy * zb.y;
            afr[ks][0] = packh2(pax, pay);
            afr[ks][1] = packh2(pcx, pcy);
            afr[ks][2] = packh2(pbx, pby);
            afr[ks][3] = packh2(pdx, pdy);
        }
    }
    qlo += __shfl_xor_sync(0xffffffffu, qlo, 1);
    qlo += __shfl_xor_sync(0xffffffffu, qlo, 2);
    qhi += __shfl_xor_sync(0xffffffffu, qhi, 1);
    qhi += __shfl_xor_sync(0xffffffffu, qhi, 2);

    // ---- staging: K (phi), V natural row-major; S_prev^T copy ----
    {
        int d = tid & 63, rg = tid >> 6;
        size_t base = ((size_t)b * TT + t0) * rowstride + (size_t)h * DD + d;
#pragma unroll 8
        for (int p = 0; p < 32; ++p) {
            int t = p * 4 + rg;
            size_t a = base + (size_t)t * rowstride;
            sK[t * S3 + d] = __float2half_rn(phi_f(kin[a]));
            sV[t * S3 + d] = __float2half_rn(vin[a]);
        }
        const uint32_t* Sp = (const uint32_t*)(g_M16 + (size_t)g * 4096);
#pragma unroll
        for (int i = tid; i < 2048; i += 256) {
            int e = i >> 5, d2 = (i & 31) * 2;
            *(uint32_t*)&sST[e * S3 + d2] = Sp[i];
        }
    }
    __syncthreads();

    // LDSM bases
    // non-trans B ([n][k] rows): n<-seg>>1, k<-seg&1
    uint32_t sTb = sm32(sST + (row8 + ((seg >> 1) << 3)) * S3 + ((seg & 1) << 3));
    uint32_t sKb = sm32(sK + (row8 + ((seg >> 1) << 3)) * S3 + ((seg & 1) << 3));
    // trans B ([k][n] rows): k<-seg&1, n<-seg>>1
    uint32_t sVb = sm32(sV + (row8 + ((seg & 1) << 3)) * S3 + ((seg >> 1) << 3));

    float acc[8][4];
#pragma unroll
    for (int i = 0; i < 8; i++)
#pragma unroll
        for (int j = 0; j < 4; j++) acc[i][j] = 0.f;

    // ---- phase 1: acc = phiQ @ S_prev ----
#pragma unroll
    for (int ks = 0; ks < 4; ++ks) {
#pragma unroll
        for (int ntp = 0; ntp < 4; ++ntp) {
            uint32_t bf4[4];
            ldsm4(bf4, sTb + (uint32_t)(16 * ntp * S3) * 2 + ks * 32);
            mma16(acc[2 * ntp], afr[ks], bf4 + 0);
            mma16(acc[2 * ntp + 1], afr[ks], bf4 + 2);
        }
    }

    // ---- phase 2: per 16-col k-tile: QK -> mask -> pack -> A@V ----
    float rs_lo = 0.f, rs_hi = 0.f;
#pragma unroll 2
    for (int j = 0; j <= bo; ++j) {
        float acc8[2][4];
#pragma unroll
        for (int u = 0; u < 2; ++u)
#pragma unroll
            for (int i = 0; i < 4; ++i) acc8[u][i] = 0.f;

        uint32_t jkoff = (uint32_t)(16 * j * S3) * 2;
#pragma unroll
        for (int ks = 0; ks < 4; ++ks) {
            uint32_t bf4[4];
            ldsm4(bf4, sKb + jkoff + ks * 32);
            mma16(acc8[0], afr[ks], bf4 + 0);
            mma16(acc8[1], afr[ks], bf4 + 2);
        }

        // mask (col <= row), rowsum, pack acc -> a-fragment (layout-exact)
        int cb0 = 16 * j + 2 * tig;
        int cb1 = cb0 + 8;
        float A00 = (cb0     <= r_lo) ? acc8[0][0] : 0.f;
        float A01 = (cb0 + 1 <= r_lo) ? acc8[0][1] : 0.f;
        float A02 = (cb0     <= r_hi) ? acc8[0][2] : 0.f;
        float A03 = (cb0 + 1 <= r_hi) ? acc8[0][3] : 0.f;
        float A10 = (cb1     <= r_lo) ? acc8[1][0] : 0.f;
        float A11 = (cb1 + 1 <= r_lo) ? acc8[1][1] : 0.f;
        float A12 = (cb1     <= r_hi) ? acc8[1][2] : 0.f;
        float A13 = (cb1 + 1 <= r_hi) ? acc8[1][3] : 0.f;
        rs_lo += A00 + A01 + A10 + A11;
        rs_hi += A02 + A03 + A12 + A13;
        uint32_t aA[4];
        aA[0] = packh2(A00, A01);
        aA[1] = packh2(A02, A03);
        aA[2] = packh2(A10, A11);
        aA[3] = packh2(A12, A13);

        // A@V: k16-range = s in [16j, 16j+16), V accessed transposed via ldsm.trans
#pragma unroll
        for (int ntp = 0; ntp < 4; ++ntp) {
            uint32_t bf4[4];
            ldsm4t(bf4, sVb + jkoff + (uint32_t)(16 * ntp) * 2);
            mma16(acc[2 * ntp], aA, bf4 + 0);
            mma16(acc[2 * ntp + 1], aA, bf4 + 2);
        }
    }

    rs_lo += __shfl_xor_sync(0xffffffffu, rs_lo, 1);
    rs_lo += __shfl_xor_sync(0xffffffffu, rs_lo, 2);
    rs_hi += __shfl_xor_sync(0xffffffffu, rs_hi, 1);
    rs_hi += __shfl_xor_sync(0xffffffffu, rs_hi, 2);

    // ---- epilogue ----
    float inv_lo = 1.f / (rs_lo + qlo + EPSV);
    float inv_hi = 1.f / (rs_hi + qhi + EPSV);
    size_t obase = ((size_t)b * TT + t0) * rowstride + (size_t)h * DD;
#pragma unroll
    for (int nt = 0; nt < 8; ++nt) {
        int c0 = nt * 8 + 2 * tig;
        *(float2*)(out + obase + (size_t)r_lo * rowstride + c0) =
            make_float2(acc[nt][0] * inv_lo, acc[nt][1] * inv_lo);
        *(float2*)(out + obase + (size_t)r_hi * rowstride + c0) =
            make_float2(acc[nt][2] * inv_hi, acc[nt][3] * inv_hi);
    }
}

// ---------------------------------------------------------------------------
extern "C" void kernel_launch(void* const* d_in, const int* in_sizes, int n_in,
                              void* d_out, int out_size) {
    const float* q = (const float*)d_in[0];
    const float* k = (const float*)d_in[1];
    const float* v = (const float*)d_in[2];
    float* out = (float*)d_out;

    cudaFuncSetAttribute(k1_kv, cudaFuncAttributeMaxDynamicSharedMemorySize, SMEM1);
    cudaFuncSetAttribute(k3_out, cudaFuncAttributeMaxDynamicSharedMemorySize, SMEM3);

    k1_kv<<<NCHUNKS, 256, SMEM1>>>(k, v);
    k2_scan<<<BHN * 8, 256>>>();
    k2_scanz<<<BHN, 64>>>();
    k3_out<<<NCHUNKS, 256, SMEM3>>>(q, k, v, out);
}